// round 1
// baseline (speedup 1.0000x reference)
#include <cuda_runtime.h>

// Problem constants
#define Hd   512
#define Bb   32
#define Ss   512
#define Wd   4
#define SPd  (Ss + 2*Wd)        // 520 padded seq length
#define CINd ((Wd+1)*Hd)        // 2560
#define MT   (Bb*Ss)            // 16384 rows
#define LLd  3

typedef unsigned long long ull;

// Scratch (static device arrays; no runtime allocation).
// Padded activation buffers double as the highway state: the highway input x
// for layer i lives in the interior of the (i+1)-parity padded buffer.
__device__ float g_pad_f[2][Bb * SPd * Hd];   // 2 x 34 MB
__device__ float g_pad_b[2][Bb * SPd * Hd];   // 2 x 34 MB
__device__ float g_tmp[MT * 2 * Hd];          // 67 MB highway proj scratch

// ---------------- packed fp32x2 helpers (sm_103a) ----------------
__device__ __forceinline__ ull f2_pack(float lo, float hi) {
    ull r; asm("mov.b64 %0, {%1, %2};" : "=l"(r) : "f"(lo), "f"(hi)); return r;
}
__device__ __forceinline__ void f2_unpack(ull v, float &lo, float &hi) {
    asm("mov.b64 {%0, %1}, %2;" : "=f"(lo), "=f"(hi) : "l"(v));
}
__device__ __forceinline__ ull f2_fma(ull a, ull b, ull c) {
    ull d; asm("fma.rn.f32x2 %0, %1, %2, %3;" : "=l"(d) : "l"(a), "l"(b), "l"(c));
    return d;
}

// Conv row mapping: logical row r (0..16383) -> padded-buffer row index
// (b*SP + t), expressed relative to an interior/base pointer. In floats.
__device__ __forceinline__ size_t crow(int r) {
    return (size_t)(r + ((r >> 9) << 3)) * Hd;
}

// ---------------- GEMM: C[M=16384, N] = epi(A @ W + bias) ----------------
// A rows are conv-mapped (overlapping windows / padded-interior rows).
// W is [K, N] row-major. CMAP: C rows conv-mapped with width 512; else plain ldc=N.
template<int K, bool CMAP, bool RELU>
__global__ __launch_bounds__(256, 2)
void gemm_k(const float* __restrict__ A, const float* __restrict__ W,
            const float* __restrict__ bias, float* __restrict__ C, int N)
{
    __shared__ __align__(16) float As[8][132];   // padded to kill STS conflicts
    __shared__ __align__(16) float Bs[8][128];

    const int tid = threadIdx.x;
    const int m0 = blockIdx.y << 7;
    const int n0 = blockIdx.x << 7;

    // A tile loader: 128 rows x 8 cols, 4 floats/thread
    const int arow = tid >> 1;
    const int acol = (tid & 1) << 2;
    const float* aptr = A + crow(m0 + arow) + acol;

    // B tile loader: 8 rows x 128 cols, 4 floats/thread
    const int brow = tid >> 5;
    const int bcol = (tid & 31) << 2;
    const float* bptr = W + (size_t)brow * N + n0 + bcol;

    const int tx = tid & 15;
    const int ty = tid >> 4;

    ull acc[8][4];
#pragma unroll
    for (int i = 0; i < 8; i++)
#pragma unroll
        for (int j = 0; j < 4; j++) acc[i][j] = 0ull;

    float4 aR = *(const float4*)(aptr);
    float4 bR = *(const float4*)(bptr);

    for (int kt = 0; kt < K; kt += 8) {
        As[acol + 0][arow] = aR.x;
        As[acol + 1][arow] = aR.y;
        As[acol + 2][arow] = aR.z;
        As[acol + 3][arow] = aR.w;
        *(float4*)&Bs[brow][bcol] = bR;
        __syncthreads();

        if (kt + 8 < K) {
            aR = *(const float4*)(aptr + kt + 8);
            bR = *(const float4*)(bptr + (size_t)(kt + 8) * N);
        }

#pragma unroll
        for (int kk = 0; kk < 8; kk++) {
            const float4 a0 = *(const float4*)&As[kk][(ty << 2)];
            const float4 a1 = *(const float4*)&As[kk][64 + (ty << 2)];
            const ulonglong2 b0 = *(const ulonglong2*)&Bs[kk][(tx << 2)];
            const ulonglong2 b1 = *(const ulonglong2*)&Bs[kk][64 + (tx << 2)];
            ull bv0 = b0.x, bv1 = b0.y, bv2 = b1.x, bv3 = b1.y;
            float av[8] = {a0.x, a0.y, a0.z, a0.w, a1.x, a1.y, a1.z, a1.w};
#pragma unroll
            for (int i = 0; i < 8; i++) {
                ull ai = f2_pack(av[i], av[i]);
                acc[i][0] = f2_fma(ai, bv0, acc[i][0]);
                acc[i][1] = f2_fma(ai, bv1, acc[i][1]);
                acc[i][2] = f2_fma(ai, bv2, acc[i][2]);
                acc[i][3] = f2_fma(ai, bv3, acc[i][3]);
            }
        }
        __syncthreads();
    }

    const float4 bb0 = *(const float4*)&bias[n0 + (tx << 2)];
    const float4 bb1 = *(const float4*)&bias[n0 + 64 + (tx << 2)];

#pragma unroll
    for (int i = 0; i < 8; i++) {
        const int rloc = (i < 4) ? ((ty << 2) + i) : (64 + (ty << 2) + (i - 4));
        const int r = m0 + rloc;
        const size_t co = CMAP ? crow(r) : (size_t)r * N;
        float4 v0, v1;
        f2_unpack(acc[i][0], v0.x, v0.y);
        f2_unpack(acc[i][1], v0.z, v0.w);
        f2_unpack(acc[i][2], v1.x, v1.y);
        f2_unpack(acc[i][3], v1.z, v1.w);
        v0.x += bb0.x; v0.y += bb0.y; v0.z += bb0.z; v0.w += bb0.w;
        v1.x += bb1.x; v1.y += bb1.y; v1.z += bb1.z; v1.w += bb1.w;
        if (RELU) {
            v0.x = fmaxf(v0.x, 0.f); v0.y = fmaxf(v0.y, 0.f);
            v0.z = fmaxf(v0.z, 0.f); v0.w = fmaxf(v0.w, 0.f);
            v1.x = fmaxf(v1.x, 0.f); v1.y = fmaxf(v1.y, 0.f);
            v1.z = fmaxf(v1.z, 0.f); v1.w = fmaxf(v1.w, 0.f);
        }
        *(float4*)&C[co + n0 + (tx << 2)]      = v0;
        *(float4*)&C[co + n0 + 64 + (tx << 2)] = v1;
    }
}

// ------------- highway elementwise: x = g*x + (1-g)*relu(nl) -------------
// xint: conv-mapped interior base (in-place). proj [M,1024] plain.
// outp (nullable): plain [M,1024] row-stride output (pre-offset for b-half).
__global__ void highway_ew(float* __restrict__ xint, const float* __restrict__ proj,
                           float* __restrict__ outp)
{
    const int idx = blockIdx.x * 256 + threadIdx.x;
    const int e = idx << 2;                 // element index into [M, 512]
    const int r = e >> 9;
    const int h = e & 511;
    const float4 nl = *(const float4*)&proj[(size_t)r * 1024 + h];
    const float4 gt = *(const float4*)&proj[(size_t)r * 1024 + 512 + h];
    const size_t xo = crow(r) + h;
    const float4 x = *(const float4*)&xint[xo];
    float4 o;
    {
        float g = 1.0f / (1.0f + __expf(-gt.x));
        o.x = g * x.x + (1.0f - g) * fmaxf(nl.x, 0.0f);
    }
    {
        float g = 1.0f / (1.0f + __expf(-gt.y));
        o.y = g * x.y + (1.0f - g) * fmaxf(nl.y, 0.0f);
    }
    {
        float g = 1.0f / (1.0f + __expf(-gt.z));
        o.z = g * x.z + (1.0f - g) * fmaxf(nl.z, 0.0f);
    }
    {
        float g = 1.0f / (1.0f + __expf(-gt.w));
        o.w = g * x.w + (1.0f - g) * fmaxf(nl.w, 0.0f);
    }
    *(float4*)&xint[xo] = o;
    if (outp) *(float4*)&outp[(size_t)r * 1024 + h] = o;
}

// ------------- fill pad rows (front = fwd_pads[i], back = bwd_pads[i]) ----
__global__ void fill_pads(float* __restrict__ pad, const float* __restrict__ fp,
                          const float* __restrict__ bp)
{
    const int idx = blockIdx.x * 256 + threadIdx.x;   // B*8*512/4 = 32768 threads
    const int e = idx << 2;
    const int b = e >> 12;       // 8*512 floats per batch
    const int rem = e & 4095;
    const int p = rem >> 9;
    const int h = rem & 511;
    float4 v;
    size_t drow;
    if (p < 4) {
        v = *(const float4*)&fp[p * Hd + h];
        drow = (size_t)(b * SPd + p);
    } else {
        v = *(const float4*)&bp[(p - 4) * Hd + h];
        drow = (size_t)(b * SPd + Wd + Ss + (p - 4));
    }
    *(float4*)&pad[drow * Hd + h] = v;
}

// ------------- copy inputs into both layer-0 padded interiors -------------
__global__ void init_copy(const float* __restrict__ in,
                          float* __restrict__ d0, float* __restrict__ d1)
{
    const int idx = blockIdx.x * 256 + threadIdx.x;
    const int e = idx << 2;
    const int r = e >> 9;
    const int h = e & 511;
    const float4 v = *(const float4*)&in[e];
    const size_t o = crow(r) + h;
    *(float4*)&d0[o] = v;
    *(float4*)&d1[o] = v;
}

extern "C" void kernel_launch(void* const* d_in, const int* in_sizes, int n_in,
                              void* d_out, int out_size)
{
    const float* inputs   = (const float*)d_in[0];
    // d_in[1] = mask (unused by reference math: mask is all ones)
    const float* fwd_pads = (const float*)d_in[2];
    const float* bwd_pads = (const float*)d_in[3];
    const float* fwd_W    = (const float*)d_in[4];
    const float* fwd_bi   = (const float*)d_in[5];
    const float* bwd_W    = (const float*)d_in[6];
    const float* bwd_bi   = (const float*)d_in[7];
    const float* fwd_hw_W = (const float*)d_in[8];
    const float* fwd_hw_b = (const float*)d_in[9];
    const float* bwd_hw_W = (const float*)d_in[10];
    const float* bwd_hw_b = (const float*)d_in[11];
    float* out = (float*)d_out;

    float *pf0, *pb0, *tmp;
    cudaGetSymbolAddress((void**)&pf0, g_pad_f);
    cudaGetSymbolAddress((void**)&pb0, g_pad_b);
    cudaGetSymbolAddress((void**)&tmp, g_tmp);
    float* pf[2] = { pf0, pf0 + (size_t)Bb * SPd * Hd };
    float* pb[2] = { pb0, pb0 + (size_t)Bb * SPd * Hd };

    const size_t INT_OFF = (size_t)Wd * Hd;   // interior offset within padded buf

    init_copy<<<8192, 256>>>(inputs, pf[0] + INT_OFF, pb[0] + INT_OFF);

    for (int i = 0; i < LLd; i++) {
        const int cur = i & 1;
        const int nxt = cur ^ 1;
        const float* fp = fwd_pads + (size_t)i * Wd * Hd;
        const float* bp = bwd_pads + (size_t)i * Wd * Hd;

        fill_pads<<<128, 256>>>(pf[cur], fp, bp);
        fill_pads<<<128, 256>>>(pb[cur], fp, bp);

        // conv GEMMs: [16384, 2560] @ [2560, 512], relu+bias, write next interior
        dim3 gc(512 / 128, MT / 128);
        gemm_k<CINd, true, true><<<gc, 256>>>(
            pf[cur], fwd_W + (size_t)i * CINd * Hd, fwd_bi + (size_t)i * Hd,
            pf[nxt] + INT_OFF, 512);
        gemm_k<CINd, true, true><<<gc, 256>>>(
            pb[cur] + INT_OFF, bwd_W + (size_t)i * CINd * Hd, bwd_bi + (size_t)i * Hd,
            pb[nxt] + INT_OFF, 512);

        // highway: 2x (GEMM [16384,512]@[512,1024] + gated combine), per direction
        dim3 gh(1024 / 128, MT / 128);
        for (int j = 0; j < 2; j++) {
            gemm_k<Hd, false, false><<<gh, 256>>>(
                pf[nxt] + INT_OFF,
                fwd_hw_W + ((size_t)i * 2 + j) * Hd * 2 * Hd,
                fwd_hw_b + ((size_t)i * 2 + j) * 2 * Hd,
                tmp, 1024);
            highway_ew<<<8192, 256>>>(
                pf[nxt] + INT_OFF, tmp,
                (j == 1) ? (out + (size_t)i * MT * 1024) : nullptr);
        }
        for (int j = 0; j < 2; j++) {
            gemm_k<Hd, false, false><<<gh, 256>>>(
                pb[nxt] + INT_OFF,
                bwd_hw_W + ((size_t)i * 2 + j) * Hd * 2 * Hd,
                bwd_hw_b + ((size_t)i * 2 + j) * 2 * Hd,
                tmp, 1024);
            highway_ew<<<8192, 256>>>(
                pb[nxt] + INT_OFF, tmp,
                (j == 1) ? (out + (size_t)i * MT * 1024 + 512) : nullptr);
        }
    }
}